// round 15
// baseline (speedup 1.0000x reference)
#include <cuda_runtime.h>
#include <stdint.h>

// Problem constants
#define VS 64
#define DEPTH_HW 256
#define IMG_H 1024
#define IMG_W 1280
#define BATCH 8
#define OUT_PER_B (VS * VS * VS)           // 262144 voxels per batch
#define N_OUT (BATCH * OUT_PER_B)          // 2097152 floats out
#define NBW (OUT_PER_B / 32)               // 8192 bit-words per batch
#define NW  (BATCH * NBW)                  // 65536 words per replica
#define R   16                             // replicas (break hot-address atomic serialization)
#define NBLK 1184                          // 8 blocks/SM x 148 SMs -- co-resident by construction

// Per-batch bit grids; 16 replicas x 256KB = 4MB. Zeroed at module load; the
// expand phase restores zero every call, so each kernel_launch / graph
// replay starts clean.
__device__ unsigned g_bits[R][NW];
// Monotonic arrival counter for the grid barrier. Never reset: each launch's
// barrier target is derived from the ticket value ((old/NBLK+1)*NBLK), so
// the counter simply advances by NBLK per launch (wrap-safe compare below).
__device__ unsigned g_arrive;

// Fused scatter + grid barrier + expand. One kernel => the ~5.5us fixed
// per-kernel floor of the separate expand launch disappears; expand runs on
// a warm machine with the bit-grid L2-resident.
//
// Co-residency guarantee (deadlock safety of the spin barrier):
// __launch_bounds__(256, 8) forces <=32 regs; smem = 0; 8 blocks x 256
// threads = 2048 threads/SM = max; so all 1184 blocks are resident
// simultaneously.
__global__ void __launch_bounds__(256, 8)
vox_fused_kernel(const float* __restrict__ depth,   // [8,256,256]
                 const float* __restrict__ ray,     // [1280*1024, 3]
                 float4* __restrict__ out)          // [8,64,64,64] as float4
{
    const int lane = threadIdx.x & 31;
    const int wid  = threadIdx.x >> 5;            // 0..7

    // ---------------- scatter phase (measured-best shape) ----------------
    // Persistent loop over the 4096 pixel tiles; warp covers a 4(y) x 8(x)
    // tile so each per-batch depth load is a single 128B line.
    for (int tile = blockIdx.x; tile < 4096; tile += NBLK) {
        const int bx = tile & 127;                // 128 x-tiles of width 8
        const int by = tile >> 7;                 // 32  y-tiles of height 32

        const int y  = by * 32 + wid * 4 + (lane & 3);   // 0..1023
        const int xr = bx * 8 + (lane >> 2);             // 0..1023

        unsigned* __restrict__ bits = g_bits[((tile << 3) + wid) & (R - 1)];

        // ray index: column-major flatten idx = x*1024 + y, x = xr + 128
        const int ridx = ((xr + 128) << 10) + y;
        const float rx = __ldg(&ray[3 * ridx + 0]);
        const float ry = __ldg(&ray[3 * ridx + 1]);
        const float rz = __ldg(&ray[3 * ridx + 2]);

        const float scale = 64.0f / 3.0f;
        const int doff = ((y >> 2) << 8) + (xr >> 2);    // depth[b, y/4, xr/4]

#pragma unroll
        for (int b = 0; b < BATCH; b++) {
            const float d = __ldg(&depth[b * (DEPTH_HW * DEPTH_HW) + doff]);

            // Replicate reference f32 op sequence exactly: mul, add, mul,
            // round-half-even. _rn intrinsics forbid FFMA contraction.
            const float px = __fmul_rn(rx, d);
            const float py = __fmul_rn(ry, d);
            const float pz = __fmul_rn(rz, d);

            const int ix = __float2int_rn(__fmul_rn(__fadd_rn(px, 1.5f), scale));
            const int iy = __float2int_rn(__fmul_rn(__fadd_rn(py, 1.5f), scale));
            const int iz = __float2int_rn(__fmul_rn(pz, scale));

            if (((unsigned)ix < 64u) & ((unsigned)iy < 64u) & ((unsigned)iz < 64u)) {
                const int lin = (((ix << 6) + iy) << 6) + iz;
                atomicOr(&bits[b * NBW + (lin >> 5)], 1u << (lin & 31));
            }
        }
    }

    // Padded columns all have depth==0 -> voxel (32,32,0), lin = 133120
    // = word 4160, bit 0, for every batch. Write into replica 0.
    if (blockIdx.x == 0 && threadIdx.x < BATCH) {
        atomicOr(&g_bits[0][threadIdx.x * NBW + 4160], 1u);
    }

    // ---------------- grid barrier ----------------
    __threadfence();        // make this block's REDGs visible device-wide
    __syncthreads();        // all warps of the block arrived
    if (threadIdx.x == 0) {
        const unsigned old    = atomicAdd(&g_arrive, 1u);
        const unsigned target = (old / NBLK + 1u) * NBLK;  // this launch's epoch end
        // Wrap-safe spin until all NBLK blocks of this launch have arrived.
        while ((int)(*(volatile unsigned*)&g_arrive - target) < 0) { }
    }
    __syncthreads();        // release all warps of the block
    __threadfence();        // order barrier observation before expand loads

    // ---------------- expand phase (measured-best warp-chunk shape) -------
    // 2048 word-chunks over 9472 warps: global warp g handles chunk g if
    // g < 2048. Each warp owns 32 consecutive words exclusively: lane l
    // accumulates word w0+l over all 16 replicas (each load one coalesced
    // 128B line), zeroes them (loads precede stores; exclusive ownership),
    // then 8 shfl rounds emit coalesced float4 stores. Word w covers output
    // float4s [8w, 8w+8) (out is [B][VS^3] floats; w encodes the batch).
    // Writes every output element -> no separate zero pass.
    const int gw = blockIdx.x * 8 + wid;          // 0..9471
    if (gw < 2048) {
        const int w0 = gw * 32;

        unsigned acc = 0;
#pragma unroll
        for (int r = 0; r < R; r++) acc |= g_bits[r][w0 + lane];

#pragma unroll
        for (int r = 0; r < R; r++) g_bits[r][w0 + lane] = 0u;

        const unsigned sh = (lane & 7) * 4;
#pragma unroll
        for (int j = 0; j < 8; j++) {
            const unsigned v = __shfl_sync(0xFFFFFFFFu, acc, j * 4 + (lane >> 3));
            float4 o;
            o.x = ((v >> (sh + 0)) & 1u) ? 1.0f : 0.0f;
            o.y = ((v >> (sh + 1)) & 1u) ? 1.0f : 0.0f;
            o.z = ((v >> (sh + 2)) & 1u) ? 1.0f : 0.0f;
            o.w = ((v >> (sh + 3)) & 1u) ? 1.0f : 0.0f;
            out[w0 * 8 + j * 32 + lane] = o;
        }
    }
}

extern "C" void kernel_launch(void* const* d_in, const int* in_sizes, int n_in,
                              void* d_out, int out_size)
{
    const float* depth = (const float*)d_in[0];
    const float* ray   = (const float*)d_in[1];
    // Defensive: identify by element count (depth = 524288, ray = 3932160)
    if (n_in >= 2 && in_sizes[0] == IMG_W * IMG_H * 3) {
        ray   = (const float*)d_in[0];
        depth = (const float*)d_in[1];
    }
    float4* out = (float4*)d_out;

    vox_fused_kernel<<<NBLK, 256>>>(depth, ray, out);
}

// round 17
// speedup vs baseline: 1.6045x; 1.6045x over previous
#include <cuda_runtime.h>
#include <stdint.h>

// Problem constants
#define VS 64
#define DEPTH_HW 256
#define IMG_H 1024
#define IMG_W 1280
#define BATCH 8
#define OUT_PER_B (VS * VS * VS)           // 262144 voxels per batch
#define N_OUT (BATCH * OUT_PER_B)          // 2097152 floats out
#define NBW (OUT_PER_B / 32)               // 8192 bit-words per batch
#define NW  (BATCH * NBW)                  // 65536 words per replica
#define R   16                             // replicas (break hot-address atomic serialization)

// Per-batch bit grids (word address includes the batch index -- spreads the
// hot near-origin voxel mass over 8x more addresses; measured essential).
// 16 replicas x 256KB = 4MB. Zeroed at module load; the expand kernel
// restores zero every call, so each kernel_launch / graph replay starts clean.
__device__ unsigned g_bits[R][NW];

// Scatter (measured-best configuration): one thread per non-padded pixel,
// 4096 blocks x 256 threads; warp covers a 4(y) x 8(x) tile so each
// per-batch depth load is a single 128B line. Tight inline loop: load depth,
// compute voxel, REDG.OR into this warp's replica. At the REDG
// lane-throughput / address-divergence floor (every structural alternative
// measured slower: STG, merge, shared-word layout, vectorized rays, tiny
// blocks, split chains, fused persistent kernel).
__global__ void __launch_bounds__(256)
vox_scatter_kernel(const float* __restrict__ depth,   // [8,256,256]
                   const float* __restrict__ ray)     // [1280*1024, 3]
{
    const int lane = threadIdx.x & 31;
    const int wid  = threadIdx.x >> 5;            // 0..7
    const int bx   = blockIdx.x & 127;            // 128 x-tiles of width 8
    const int by   = blockIdx.x >> 7;             // 32  y-tiles of height 32

    const int y  = by * 32 + wid * 4 + (lane & 3);   // 0..1023
    const int xr = bx * 8 + (lane >> 2);             // 0..1023 (non-padded x)

    unsigned* __restrict__ bits = g_bits[((blockIdx.x << 3) + wid) & (R - 1)];

    // ray index: column-major flatten idx = x*1024 + y, x = xr + 128
    const int ridx = ((xr + 128) << 10) + y;
    const float rx = __ldg(&ray[3 * ridx + 0]);
    const float ry = __ldg(&ray[3 * ridx + 1]);
    const float rz = __ldg(&ray[3 * ridx + 2]);

    const float scale = 64.0f / 3.0f;
    const int doff = ((y >> 2) << 8) + (xr >> 2);    // depth[b, y/4, xr/4]

#pragma unroll
    for (int b = 0; b < BATCH; b++) {
        const float d = __ldg(&depth[b * (DEPTH_HW * DEPTH_HW) + doff]);

        // Replicate reference f32 op sequence exactly: mul, add, mul,
        // round-half-even. _rn intrinsics forbid FFMA contraction (which
        // would perturb points near .5 rounding boundaries).
        const float px = __fmul_rn(rx, d);
        const float py = __fmul_rn(ry, d);
        const float pz = __fmul_rn(rz, d);

        const int ix = __float2int_rn(__fmul_rn(__fadd_rn(px, 1.5f), scale));
        const int iy = __float2int_rn(__fmul_rn(__fadd_rn(py, 1.5f), scale));
        const int iz = __float2int_rn(__fmul_rn(pz, scale));

        if (((unsigned)ix < 64u) & ((unsigned)iy < 64u) & ((unsigned)iz < 64u)) {
            const int lin = (((ix << 6) + iy) << 6) + iz;
            atomicOr(&bits[b * NBW + (lin >> 5)], 1u << (lin & 31));
        }
    }

    // Padded columns all have depth==0 -> voxel (32,32,0), lin = 133120
    // = word 4160, bit 0, for every batch. Write into replica 0.
    if (blockIdx.x == 0 && threadIdx.x < BATCH) {
        atomicOr(&g_bits[0][threadIdx.x * NBW + 4160], 1u);
    }
}

// Expand (measured-best warp-chunk shape): each warp owns 32 consecutive
// words exclusively (all replicas). Lane l accumulates word w0+l over all 16
// replicas -- every load is one fully-coalesced 128B line per warp. Zeroing
// mirrors the loads (16 coalesced stores; loads precede stores in program
// order, exclusive ownership => no race). Output: 8 rounds; round j fetches
// the source word via shfl (src lane 4j + l/8), extracts this lane's 4-bit
// nibble, writes one coalesced float4. Word w maps to output float4s
// [8w, 8w+8) since out is [B][VS^3] = [NW*32] floats and w already encodes
// the batch. Writes every output element -> no separate zero pass. Runtime
// is dominated by a ~5.5us fixed per-kernel floor (half-work variant
// measured 5.76us), so no further shape change pays.
__global__ void __launch_bounds__(256)
vox_expand_kernel(float4* __restrict__ out)
{
    const int lane = threadIdx.x & 31;
    const int warp = (blockIdx.x * 256 + threadIdx.x) >> 5;   // 0..2047
    const int w0   = warp * 32;

    unsigned acc = 0;
#pragma unroll
    for (int r = 0; r < R; r++) acc |= g_bits[r][w0 + lane];

#pragma unroll
    for (int r = 0; r < R; r++) g_bits[r][w0 + lane] = 0u;

    const unsigned sh = (lane & 7) * 4;
#pragma unroll
    for (int j = 0; j < 8; j++) {
        const unsigned v = __shfl_sync(0xFFFFFFFFu, acc, j * 4 + (lane >> 3));
        float4 o;
        o.x = ((v >> (sh + 0)) & 1u) ? 1.0f : 0.0f;
        o.y = ((v >> (sh + 1)) & 1u) ? 1.0f : 0.0f;
        o.z = ((v >> (sh + 2)) & 1u) ? 1.0f : 0.0f;
        o.w = ((v >> (sh + 3)) & 1u) ? 1.0f : 0.0f;
        out[w0 * 8 + j * 32 + lane] = o;
    }
}

extern "C" void kernel_launch(void* const* d_in, const int* in_sizes, int n_in,
                              void* d_out, int out_size)
{
    const float* depth = (const float*)d_in[0];
    const float* ray   = (const float*)d_in[1];
    // Defensive: identify by element count (depth = 524288, ray = 3932160)
    if (n_in >= 2 && in_sizes[0] == IMG_W * IMG_H * 3) {
        ray   = (const float*)d_in[0];
        depth = (const float*)d_in[1];
    }
    float* out = (float*)d_out;

    vox_scatter_kernel<<<4096, 256>>>(depth, ray);
    // 65536 words / 32 per warp = 2048 warps = 256 blocks of 256 threads
    vox_expand_kernel<<<256, 256>>>((float4*)out);
}